// round 1
// baseline (speedup 1.0000x reference)
#include <cuda_runtime.h>
#include <math.h>

// ---------------- problem constants ----------------
#define TT   128
#define BB   32
#define NTB  4096            // T*B
#define HID  256
#define FEAT 512
#define FLAT 3136            // 64*7*7
#define NACT 6

// output layout (flattened tuple): logits[4096*6], v[4096], h[32*256], c[32*256]
#define OUT_V    24576
#define OUT_H    28672
#define OUT_C    36864

// ---------------- scratch (device globals; no allocations allowed) ----------------
__device__ float g_c1[(size_t)NTB*32*20*20];   // 210 MB
__device__ float g_c2[(size_t)NTB*64*9*9];     //  85 MB
__device__ float g_c3[(size_t)NTB*64*7*7];     //  51 MB
__device__ float g_feat[(size_t)NTB*FEAT];     //   8 MB
__device__ float g_gx[(size_t)NTB*4*HID];      //  16 MB
__device__ float g_hs[(size_t)NTB*HID];        //   4 MB
__device__ float g_h[BB*HID];
__device__ unsigned g_bar;
__device__ unsigned g_exit;

// ======================================================================
// conv1: in (n,3,84,84)/255 -> out (n,32,20,20), k=8, stride 4, relu
// one block per image. smem: image (3*84*84) + weights [c][ky][kx][32]
// ======================================================================
#define C1_SMEM ((21168 + 6144) * 4)
__global__ void conv1_kernel(const float* __restrict__ img,
                             const float* __restrict__ w,
                             const float* __restrict__ bias) {
    extern __shared__ float sm[];
    float* im = sm;           // 21168
    float* ws = sm + 21168;   // 6144
    int n = blockIdx.x;
    const float* src = img + (size_t)n * 21168;
    for (int i = threadIdx.x; i < 21168; i += 256) im[i] = src[i] * (1.0f / 255.0f);
    for (int i = threadIdx.x; i < 6144; i += 256) {
        int co = i & 31; int rest = i >> 5;
        int kx = rest & 7; rest >>= 3;
        int ky = rest & 7; int c = rest >> 3;
        ws[i] = w[((co * 3 + c) * 8 + ky) * 8 + kx];
    }
    __syncthreads();

    for (int pos = threadIdx.x; pos < 400; pos += 256) {
        int oy = pos / 20, ox = pos % 20;
        float acc[32];
#pragma unroll
        for (int i = 0; i < 32; i++) acc[i] = 0.f;
        for (int c = 0; c < 3; c++) {
#pragma unroll
            for (int ky = 0; ky < 8; ky++) {
                const float* irow = &im[(c * 84 + oy * 4 + ky) * 84 + ox * 4];
                float r[8];
#pragma unroll
                for (int kx = 0; kx < 8; kx++) r[kx] = irow[kx];
                const float* wrow = &ws[((c * 8 + ky) * 8) * 32];
#pragma unroll
                for (int kx = 0; kx < 8; kx++) {
                    const float4* w4 = (const float4*)(wrow + kx * 32);
                    float rv = r[kx];
#pragma unroll
                    for (int q = 0; q < 8; q++) {
                        float4 v = w4[q];
                        acc[q * 4 + 0] += rv * v.x;
                        acc[q * 4 + 1] += rv * v.y;
                        acc[q * 4 + 2] += rv * v.z;
                        acc[q * 4 + 3] += rv * v.w;
                    }
                }
            }
        }
        float* dst = g_c1 + (size_t)n * 12800 + pos;
#pragma unroll
        for (int co = 0; co < 32; co++) {
            float v = acc[co] + bias[co];
            dst[co * 400] = fmaxf(v, 0.f);
        }
    }
}

// ======================================================================
// conv2: in (n,32,20,20) -> out (n,64,9,9), k=4, stride 2, relu
// ======================================================================
#define C2_SMEM ((12800 + 32768) * 4)
__global__ void conv2_kernel(const float* __restrict__ w,
                             const float* __restrict__ bias) {
    extern __shared__ float sm[];
    float* in = sm;            // 32*400
    float* ws = sm + 12800;    // [c][ky][kx][64]
    int n = blockIdx.x;
    const float* src = g_c1 + (size_t)n * 12800;
    for (int i = threadIdx.x; i < 12800; i += 256) in[i] = src[i];
    for (int i = threadIdx.x; i < 32768; i += 256) {
        int co = i & 63; int rest = i >> 6;
        int kx = rest & 3; rest >>= 2;
        int ky = rest & 3; int c = rest >> 2;
        ws[i] = w[((co * 32 + c) * 4 + ky) * 4 + kx];
    }
    __syncthreads();

    for (int item = threadIdx.x; item < 324; item += 256) {  // 81 pos x 4 co-tiles
        int pos = item % 81, cot = item / 81;
        int oy = pos / 9, ox = pos % 9;
        float acc[16];
#pragma unroll
        for (int i = 0; i < 16; i++) acc[i] = 0.f;
        for (int c = 0; c < 32; c++) {
#pragma unroll
            for (int ky = 0; ky < 4; ky++) {
                const float* irow = &in[(c * 20 + oy * 2 + ky) * 20 + ox * 2];
                float r[4];
#pragma unroll
                for (int kx = 0; kx < 4; kx++) r[kx] = irow[kx];
                const float4* w4 = (const float4*)&ws[((c * 4 + ky) * 4) * 64 + cot * 16];
#pragma unroll
                for (int kx = 0; kx < 4; kx++) {
                    float rv = r[kx];
#pragma unroll
                    for (int q = 0; q < 4; q++) {
                        float4 v = w4[kx * 16 + q];
                        acc[q * 4 + 0] += rv * v.x;
                        acc[q * 4 + 1] += rv * v.y;
                        acc[q * 4 + 2] += rv * v.z;
                        acc[q * 4 + 3] += rv * v.w;
                    }
                }
            }
        }
        float* dst = g_c2 + (size_t)n * 5184 + pos;
#pragma unroll
        for (int i = 0; i < 16; i++) {
            int co = cot * 16 + i;
            float v = acc[i] + bias[co];
            dst[co * 81] = fmaxf(v, 0.f);
        }
    }
}

// ======================================================================
// conv3: in (n,64,9,9) -> out (n,64,7,7), k=3, stride 1, relu
// ======================================================================
#define C3_SMEM ((5184 + 36864) * 4)
__global__ void conv3_kernel(const float* __restrict__ w,
                             const float* __restrict__ bias) {
    extern __shared__ float sm[];
    float* in = sm;            // 64*81
    float* ws = sm + 5184;     // [c][ky][kx][64]
    int n = blockIdx.x;
    const float* src = g_c2 + (size_t)n * 5184;
    for (int i = threadIdx.x; i < 5184; i += 256) in[i] = src[i];
    for (int i = threadIdx.x; i < 36864; i += 256) {
        int co = i & 63; int rest = i >> 6;
        int kx = rest % 3; rest /= 3;
        int ky = rest % 3; int c = rest / 3;
        ws[i] = w[((co * 64 + c) * 3 + ky) * 3 + kx];
    }
    __syncthreads();

    int item = threadIdx.x;   // 49 pos x 4 co-tiles = 196 items
    if (item < 196) {
        int pos = item % 49, cot = item / 49;
        int oy = pos / 7, ox = pos % 7;
        float acc[16];
#pragma unroll
        for (int i = 0; i < 16; i++) acc[i] = 0.f;
        for (int c = 0; c < 64; c++) {
#pragma unroll
            for (int ky = 0; ky < 3; ky++) {
                const float* irow = &in[(c * 9 + oy + ky) * 9 + ox];
                float r[3];
#pragma unroll
                for (int kx = 0; kx < 3; kx++) r[kx] = irow[kx];
                const float4* w4 = (const float4*)&ws[((c * 3 + ky) * 3) * 64 + cot * 16];
#pragma unroll
                for (int kx = 0; kx < 3; kx++) {
                    float rv = r[kx];
#pragma unroll
                    for (int q = 0; q < 4; q++) {
                        float4 v = w4[kx * 16 + q];
                        acc[q * 4 + 0] += rv * v.x;
                        acc[q * 4 + 1] += rv * v.y;
                        acc[q * 4 + 2] += rv * v.z;
                        acc[q * 4 + 3] += rv * v.w;
                    }
                }
            }
        }
        float* dst = g_c3 + (size_t)n * 3136 + pos;
#pragma unroll
        for (int i = 0; i < 16; i++) {
            int co = cot * 16 + i;
            float v = acc[i] + bias[co];
            dst[co * 49] = fmaxf(v, 0.f);
        }
    }
}

// ======================================================================
// GEMM: C[M,N] = A[M,K] @ Bw[N,K]^T + b1 (+ b2), optional relu
// 128x128 CTA tile, 8x8 microtile, BK=16
// ======================================================================
template <bool RELU>
__global__ void gemm_kernel(const float* __restrict__ A,
                            const float* __restrict__ Bw,
                            const float* __restrict__ bias1,
                            const float* __restrict__ bias2,
                            float* __restrict__ C,
                            int M, int N, int K) {
    __shared__ float As[16][132];
    __shared__ float Bs[16][132];
    int bm = blockIdx.y * 128, bn = blockIdx.x * 128;
    int t = threadIdx.x;
    int lr = t >> 1, lc = (t & 1) * 8;
    int tx = t & 15, ty = t >> 4;
    float acc[8][8];
#pragma unroll
    for (int i = 0; i < 8; i++)
#pragma unroll
        for (int j = 0; j < 8; j++) acc[i][j] = 0.f;

    for (int k0 = 0; k0 < K; k0 += 16) {
        const float4* ag = (const float4*)(A + (size_t)(bm + lr) * K + k0 + lc);
        float4 a0 = ag[0], a1 = ag[1];
        As[lc + 0][lr] = a0.x; As[lc + 1][lr] = a0.y; As[lc + 2][lr] = a0.z; As[lc + 3][lr] = a0.w;
        As[lc + 4][lr] = a1.x; As[lc + 5][lr] = a1.y; As[lc + 6][lr] = a1.z; As[lc + 7][lr] = a1.w;
        const float4* bg = (const float4*)(Bw + (size_t)(bn + lr) * K + k0 + lc);
        float4 b0 = bg[0], b1 = bg[1];
        Bs[lc + 0][lr] = b0.x; Bs[lc + 1][lr] = b0.y; Bs[lc + 2][lr] = b0.z; Bs[lc + 3][lr] = b0.w;
        Bs[lc + 4][lr] = b1.x; Bs[lc + 5][lr] = b1.y; Bs[lc + 6][lr] = b1.z; Bs[lc + 7][lr] = b1.w;
        __syncthreads();
#pragma unroll
        for (int kk = 0; kk < 16; kk++) {
            float a[8], b[8];
            *(float4*)&a[0] = *(const float4*)&As[kk][ty * 8];
            *(float4*)&a[4] = *(const float4*)&As[kk][ty * 8 + 4];
            *(float4*)&b[0] = *(const float4*)&Bs[kk][tx * 8];
            *(float4*)&b[4] = *(const float4*)&Bs[kk][tx * 8 + 4];
#pragma unroll
            for (int i = 0; i < 8; i++)
#pragma unroll
                for (int j = 0; j < 8; j++) acc[i][j] += a[i] * b[j];
        }
        __syncthreads();
    }

#pragma unroll
    for (int i = 0; i < 8; i++) {
        int row = bm + ty * 8 + i;
#pragma unroll
        for (int j = 0; j < 8; j++) {
            int col = bn + tx * 8 + j;
            float v = acc[i][j] + bias1[col];
            if (bias2) v += bias2[col];
            if (RELU) v = fmaxf(v, 0.f);
            C[(size_t)row * N + col] = v;
        }
    }
}

// ======================================================================
// persistent LSTM: 64 CTAs, each owns 4 hidden units (all 4 gates).
// gx precomputed (x@W_ih^T + b_ih + b_hh). One grid barrier per step.
// ======================================================================
#define NBLK 64
#define LSTM_SMEM (12992 * 4)
__device__ __forceinline__ float sigmoidf(float x) { return 1.f / (1.f + expf(-x)); }

__global__ void lstm_kernel(const float* __restrict__ done,
                            const float* __restrict__ h0,
                            const float* __restrict__ c0,
                            const float* __restrict__ whh,
                            float* __restrict__ out) {
    extern __shared__ float sm[];
    float* w_s = sm;             // [k=256][r=16]  (transposed)
    float* h_s = sm + 4096;      // [32][257]
    float* c_s = h_s + 32 * 257; // [128]  (b*4+jj)
    float* m_s = c_s + 128;      // [32]
    float* g_s = m_s + 32;       // [32][16]
    int t = threadIdx.x, blk = blockIdx.x;
    int j0 = blk * 4;

    // W_hh rows for our 16 gate rows, transposed: w_s[k*16 + r]
    for (int i = t; i < 4096; i += 256) {
        int k = i >> 4, r = i & 15;
        int q = r >> 2, jj = r & 3;
        w_s[i] = whh[(size_t)(q * HID + j0 + jj) * HID + k];
    }
    if (t < 128) {
        int b = t >> 2, jj = t & 3;
        c_s[t] = c0[b * HID + j0 + jj];
    }
    __syncthreads();

    unsigned target = 0;
    for (int step = 0; step < TT; step++) {
        if (t < 32) m_s[t] = 1.0f - done[step * BB + t];
        __syncthreads();

        const float* hsrc = (step == 0) ? h0 : g_h;
        for (int i = t; i < BB * HID; i += 256) {
            int b = i >> 8, k = i & 255;
            h_s[b * 257 + k] = hsrc[i] * m_s[b];
        }
        __syncthreads();

        // gates: 128 threads, each computes 4 gate rows (one q) for one batch b
        if (t < 128) {
            int b = t & 31, rq = t >> 5;   // rq = gate index q
            float4 acc = *(const float4*)&g_gx[(size_t)(step * BB + b) * 4 * HID + rq * HID + j0];
            const float* hp = &h_s[b * 257];
#pragma unroll 4
            for (int k = 0; k < HID; k++) {
                float hv = hp[k];
                float4 wv = *(const float4*)&w_s[k * 16 + rq * 4];
                acc.x += hv * wv.x;
                acc.y += hv * wv.y;
                acc.z += hv * wv.z;
                acc.w += hv * wv.w;
            }
            g_s[b * 16 + rq * 4 + 0] = acc.x;
            g_s[b * 16 + rq * 4 + 1] = acc.y;
            g_s[b * 16 + rq * 4 + 2] = acc.z;
            g_s[b * 16 + rq * 4 + 3] = acc.w;
        }
        __syncthreads();

        // update: 128 threads, one (b, jj) each
        if (t < 128) {
            int b = t >> 2, jj = t & 3;
            float gi = g_s[b * 16 + 0 * 4 + jj];
            float gf = g_s[b * 16 + 1 * 4 + jj];
            float gg = g_s[b * 16 + 2 * 4 + jj];
            float go = g_s[b * 16 + 3 * 4 + jj];
            float I = sigmoidf(gi);
            float F = sigmoidf(gf);
            float G = tanhf(gg);
            float O = sigmoidf(go);
            float c_new = F * (m_s[b] * c_s[t]) + I * G;
            c_s[t] = c_new;
            float h_new = O * tanhf(c_new);
            g_h[b * HID + j0 + jj] = h_new;
            g_hs[(size_t)(step * BB + b) * HID + j0 + jj] = h_new;
            if (step == TT - 1) {
                out[OUT_H + b * HID + j0 + jj] = h_new;
                out[OUT_C + b * HID + j0 + jj] = c_new;
            }
        }
        __threadfence();
        __syncthreads();
        if (t == 0) {
            atomicAdd(&g_bar, 1u);
            target += NBLK;
            while (atomicAdd(&g_bar, 0u) < target) { }
        }
        __syncthreads();
    }

    // reset barrier state for next graph replay (last CTA to exit resets)
    if (t == 0) {
        unsigned v = atomicAdd(&g_exit, 1u);
        if (v == NBLK - 1) {
            atomicExch(&g_exit, 0u);
            atomicExch(&g_bar, 0u);
            __threadfence();
        }
    }
}

// ======================================================================
// heads: logits = h@pol_w^T + pol_b ; v = h@val_w^T + val_b
// one warp per row; 8 rows per block
// ======================================================================
__global__ void heads_kernel(const float* __restrict__ pw,
                             const float* __restrict__ pb,
                             const float* __restrict__ vw,
                             const float* __restrict__ vb,
                             float* __restrict__ out) {
    __shared__ float ws[7 * 256];
    int t = threadIdx.x;
    for (int i = t; i < 6 * 256; i += 256) ws[i] = pw[i];
    if (t < 256) ws[1536 + t] = vw[t];
    __syncthreads();

    int warp = t >> 5, lane = t & 31;
    int row = blockIdx.x * 8 + warp;
    const float* hrow = g_hs + (size_t)row * 256;
    float p[7];
#pragma unroll
    for (int a = 0; a < 7; a++) p[a] = 0.f;
    for (int k = lane; k < 256; k += 32) {
        float hv = hrow[k];
#pragma unroll
        for (int a = 0; a < 7; a++) p[a] += hv * ws[a * 256 + k];
    }
#pragma unroll
    for (int a = 0; a < 7; a++)
#pragma unroll
        for (int off = 16; off; off >>= 1)
            p[a] += __shfl_xor_sync(0xffffffffu, p[a], off);
    if (lane == 0) {
#pragma unroll
        for (int a = 0; a < 6; a++) out[(size_t)row * 6 + a] = p[a] + pb[a];
        out[OUT_V + row] = p[6] + vb[0];
    }
}

// ======================================================================
// launch
// ======================================================================
extern "C" void kernel_launch(void* const* d_in, const int* in_sizes, int n_in,
                              void* d_out, int out_size) {
    const float* image = (const float*)d_in[0];
    const float* done  = (const float*)d_in[1];
    const float* h0    = (const float*)d_in[2];
    const float* c0    = (const float*)d_in[3];
    const float* c1w   = (const float*)d_in[4];
    const float* c1b   = (const float*)d_in[5];
    const float* c2w   = (const float*)d_in[6];
    const float* c2b   = (const float*)d_in[7];
    const float* c3w   = (const float*)d_in[8];
    const float* c3b   = (const float*)d_in[9];
    const float* fcw   = (const float*)d_in[10];
    const float* fcb   = (const float*)d_in[11];
    const float* wih   = (const float*)d_in[12];
    const float* whh   = (const float*)d_in[13];
    const float* bih   = (const float*)d_in[14];
    const float* bhh   = (const float*)d_in[15];
    const float* polw  = (const float*)d_in[16];
    const float* polb  = (const float*)d_in[17];
    const float* valw  = (const float*)d_in[18];
    const float* valb  = (const float*)d_in[19];
    float* out = (float*)d_out;

    cudaFuncSetAttribute(conv1_kernel, cudaFuncAttributeMaxDynamicSharedMemorySize, C1_SMEM);
    cudaFuncSetAttribute(conv2_kernel, cudaFuncAttributeMaxDynamicSharedMemorySize, C2_SMEM);
    cudaFuncSetAttribute(conv3_kernel, cudaFuncAttributeMaxDynamicSharedMemorySize, C3_SMEM);
    cudaFuncSetAttribute(lstm_kernel,  cudaFuncAttributeMaxDynamicSharedMemorySize, LSTM_SMEM);

    void *p_c3, *p_feat, *p_gx;
    cudaGetSymbolAddress(&p_c3, g_c3);
    cudaGetSymbolAddress(&p_feat, g_feat);
    cudaGetSymbolAddress(&p_gx, g_gx);

    conv1_kernel<<<NTB, 256, C1_SMEM>>>(image, c1w, c1b);
    conv2_kernel<<<NTB, 256, C2_SMEM>>>(c2w, c2b);
    conv3_kernel<<<NTB, 256, C3_SMEM>>>(c3w, c3b);

    // feats = relu(flat @ fc_w^T + fc_b)   [4096,512]
    gemm_kernel<true><<<dim3(FEAT / 128, NTB / 128), 256>>>(
        (const float*)p_c3, fcw, fcb, nullptr, (float*)p_feat, NTB, FEAT, FLAT);

    // gates_x = feats @ w_ih^T + b_ih + b_hh   [4096,1024]
    gemm_kernel<false><<<dim3((4 * HID) / 128, NTB / 128), 256>>>(
        (const float*)p_feat, wih, bih, bhh, (float*)p_gx, NTB, 4 * HID, FEAT);

    lstm_kernel<<<NBLK, 256, LSTM_SMEM>>>(done, h0, c0, whh, out);

    heads_kernel<<<NTB / 8, 256>>>(polw, polb, valw, valb, out);
}

// round 2
// speedup vs baseline: 1.0965x; 1.0965x over previous
#include <cuda_runtime.h>
#include <math.h>

// ---------------- problem constants ----------------
#define TT   128
#define BB   32
#define NTB  4096            // T*B
#define HID  256
#define FEAT 512
#define FLAT 3136            // 64*7*7
#define NACT 6

// output layout (flattened tuple): logits[4096*6], v[4096], h[32*256], c[32*256]
#define OUT_V    24576
#define OUT_H    28672
#define OUT_C    36864

// ---------------- scratch (device globals; no allocations allowed) ----------------
__device__ float g_c1[(size_t)NTB*32*20*20];   // 210 MB
__device__ float g_c2[(size_t)NTB*64*9*9];     //  85 MB
__device__ float g_c3[(size_t)NTB*64*7*7];     //  51 MB
__device__ float g_feat[(size_t)NTB*FEAT];     //   8 MB
__device__ float g_gx[(size_t)NTB*4*HID];      //  16 MB
__device__ float g_hs[(size_t)NTB*HID];        //   4 MB
__device__ float g_h[BB*HID];
__device__ unsigned g_bar;
__device__ unsigned g_exit;

// ======================================================================
// conv1: in (n,3,84,84)/255 -> out (n,32,20,20), k=8, stride 4, relu
// one block per image, 400 threads = 1 output position each (balanced).
// 1/255 folded into the smem weight copy.
// ======================================================================
#define C1_THREADS 400
#define C1_SMEM ((21168 + 6144) * 4)
__global__ void conv1_kernel(const float* __restrict__ img,
                             const float* __restrict__ w,
                             const float* __restrict__ bias) {
    extern __shared__ float sm[];
    float* im = sm;           // 21168
    float* ws = sm + 21168;   // 6144
    int n = blockIdx.x;
    const float* src = img + (size_t)n * 21168;
    for (int i = threadIdx.x; i < 21168; i += C1_THREADS) im[i] = src[i];
    for (int i = threadIdx.x; i < 6144; i += C1_THREADS) {
        int co = i & 31; int rest = i >> 5;
        int kx = rest & 7; rest >>= 3;
        int ky = rest & 7; int c = rest >> 3;
        ws[i] = w[((co * 3 + c) * 8 + ky) * 8 + kx] * (1.0f / 255.0f);
    }
    __syncthreads();

    int pos = threadIdx.x;   // exactly 400 positions
    {
        int oy = pos / 20, ox = pos % 20;
        float acc[32];
#pragma unroll
        for (int i = 0; i < 32; i++) acc[i] = 0.f;
        for (int c = 0; c < 3; c++) {
#pragma unroll
            for (int ky = 0; ky < 8; ky++) {
                const float* irow = &im[(c * 84 + oy * 4 + ky) * 84 + ox * 4];
                float r[8];
#pragma unroll
                for (int kx = 0; kx < 8; kx++) r[kx] = irow[kx];
                const float* wrow = &ws[((c * 8 + ky) * 8) * 32];
#pragma unroll
                for (int kx = 0; kx < 8; kx++) {
                    const float4* w4 = (const float4*)(wrow + kx * 32);
                    float rv = r[kx];
#pragma unroll
                    for (int q = 0; q < 8; q++) {
                        float4 v = w4[q];
                        acc[q * 4 + 0] += rv * v.x;
                        acc[q * 4 + 1] += rv * v.y;
                        acc[q * 4 + 2] += rv * v.z;
                        acc[q * 4 + 3] += rv * v.w;
                    }
                }
            }
        }
        float* dst = g_c1 + (size_t)n * 12800 + pos;
#pragma unroll
        for (int co = 0; co < 32; co++) {
            float v = acc[co] + bias[co];
            dst[co * 400] = fmaxf(v, 0.f);
        }
    }
}

// ======================================================================
// conv2: in (n,32,20,20) -> out (n,64,9,9), k=4, stride 2, relu
// 352 threads; 324 items (81 pos x 4 co-tiles of 16), 1 item per thread.
// ======================================================================
#define C2_THREADS 352
#define C2_SMEM ((12800 + 32768) * 4)
__global__ void conv2_kernel(const float* __restrict__ w,
                             const float* __restrict__ bias) {
    extern __shared__ float sm[];
    float* in = sm;            // 32*400
    float* ws = sm + 12800;    // [c][ky][kx][64]
    int n = blockIdx.x;
    const float* src = g_c1 + (size_t)n * 12800;
    for (int i = threadIdx.x; i < 12800; i += C2_THREADS) in[i] = src[i];
    for (int i = threadIdx.x; i < 32768; i += C2_THREADS) {
        int co = i & 63; int rest = i >> 6;
        int kx = rest & 3; rest >>= 2;
        int ky = rest & 3; int c = rest >> 2;
        ws[i] = w[((co * 32 + c) * 4 + ky) * 4 + kx];
    }
    __syncthreads();

    int item = threadIdx.x;
    if (item < 324) {
        int pos = item % 81, cot = item / 81;
        int oy = pos / 9, ox = pos % 9;
        float acc[16];
#pragma unroll
        for (int i = 0; i < 16; i++) acc[i] = 0.f;
        for (int c = 0; c < 32; c++) {
#pragma unroll
            for (int ky = 0; ky < 4; ky++) {
                const float* irow = &in[(c * 20 + oy * 2 + ky) * 20 + ox * 2];
                float r[4];
#pragma unroll
                for (int kx = 0; kx < 4; kx++) r[kx] = irow[kx];
                const float4* w4 = (const float4*)&ws[((c * 4 + ky) * 4) * 64 + cot * 16];
#pragma unroll
                for (int kx = 0; kx < 4; kx++) {
                    float rv = r[kx];
#pragma unroll
                    for (int q = 0; q < 4; q++) {
                        float4 v = w4[kx * 16 + q];
                        acc[q * 4 + 0] += rv * v.x;
                        acc[q * 4 + 1] += rv * v.y;
                        acc[q * 4 + 2] += rv * v.z;
                        acc[q * 4 + 3] += rv * v.w;
                    }
                }
            }
        }
        float* dst = g_c2 + (size_t)n * 5184 + pos;
#pragma unroll
        for (int i = 0; i < 16; i++) {
            int co = cot * 16 + i;
            float v = acc[i] + bias[co];
            dst[co * 81] = fmaxf(v, 0.f);
        }
    }
}

// ======================================================================
// conv3: in (n,64,9,9) -> out (n,64,7,7), k=3, stride 1, relu
// 416 threads; 392 items (49 pos x 8 co-tiles of 8), 1 item per thread.
// ======================================================================
#define C3_THREADS 416
#define C3_SMEM ((5184 + 36864) * 4)
__global__ void conv3_kernel(const float* __restrict__ w,
                             const float* __restrict__ bias) {
    extern __shared__ float sm[];
    float* in = sm;            // 64*81
    float* ws = sm + 5184;     // [c][ky][kx][64]
    int n = blockIdx.x;
    const float* src = g_c2 + (size_t)n * 5184;
    for (int i = threadIdx.x; i < 5184; i += C3_THREADS) in[i] = src[i];
    for (int i = threadIdx.x; i < 36864; i += C3_THREADS) {
        int co = i & 63; int rest = i >> 6;
        int kx = rest % 3; rest /= 3;
        int ky = rest % 3; int c = rest / 3;
        ws[i] = w[((co * 64 + c) * 3 + ky) * 3 + kx];
    }
    __syncthreads();

    int item = threadIdx.x;   // 49 pos x 8 co-tiles of 8ch = 392 items
    if (item < 392) {
        int pos = item % 49, cot = item / 49;
        int oy = pos / 7, ox = pos % 7;
        float acc[8];
#pragma unroll
        for (int i = 0; i < 8; i++) acc[i] = 0.f;
        for (int c = 0; c < 64; c++) {
#pragma unroll
            for (int ky = 0; ky < 3; ky++) {
                const float* irow = &in[(c * 9 + oy + ky) * 9 + ox];
                float r[3];
#pragma unroll
                for (int kx = 0; kx < 3; kx++) r[kx] = irow[kx];
#pragma unroll
                for (int kx = 0; kx < 3; kx++) {
                    const float4* w4 = (const float4*)&ws[((c * 3 + ky) * 3 + kx) * 64 + cot * 8];
                    float rv = r[kx];
                    float4 v0 = w4[0], v1 = w4[1];
                    acc[0] += rv * v0.x; acc[1] += rv * v0.y;
                    acc[2] += rv * v0.z; acc[3] += rv * v0.w;
                    acc[4] += rv * v1.x; acc[5] += rv * v1.y;
                    acc[6] += rv * v1.z; acc[7] += rv * v1.w;
                }
            }
        }
        float* dst = g_c3 + (size_t)n * 3136 + pos;
#pragma unroll
        for (int i = 0; i < 8; i++) {
            int co = cot * 8 + i;
            float v = acc[i] + bias[co];
            dst[co * 49] = fmaxf(v, 0.f);
        }
    }
}

// ======================================================================
// GEMM: C[M,N] = A[M,K] @ Bw[N,K]^T + b1 (+ b2), optional relu
// BM x 128 CTA tile (BM = 64 or 128), BK=16, 256 threads.
// ======================================================================
template <int BM, bool RELU>
__global__ void gemm_kernel(const float* __restrict__ A,
                            const float* __restrict__ Bw,
                            const float* __restrict__ bias1,
                            const float* __restrict__ bias2,
                            float* __restrict__ C,
                            int M, int N, int K) {
    constexpr int MI = BM / 16;               // rows per thread (8 or 4)
    __shared__ float As[16][BM + 4];
    __shared__ float Bs[16][132];
    int bm = blockIdx.y * BM, bn = blockIdx.x * 128;
    int t = threadIdx.x;
    int tx = t & 15, ty = t >> 4;
    float acc[MI][8];
#pragma unroll
    for (int i = 0; i < MI; i++)
#pragma unroll
        for (int j = 0; j < 8; j++) acc[i][j] = 0.f;

    for (int k0 = 0; k0 < K; k0 += 16) {
        if (BM == 128) {
            int lr = t >> 1, lc = (t & 1) * 8;
            const float4* ag = (const float4*)(A + (size_t)(bm + lr) * K + k0 + lc);
            float4 a0 = ag[0], a1 = ag[1];
            As[lc + 0][lr] = a0.x; As[lc + 1][lr] = a0.y; As[lc + 2][lr] = a0.z; As[lc + 3][lr] = a0.w;
            As[lc + 4][lr] = a1.x; As[lc + 5][lr] = a1.y; As[lc + 6][lr] = a1.z; As[lc + 7][lr] = a1.w;
        } else {
            int lr = t >> 2, lc = (t & 3) * 4;
            const float4* ag = (const float4*)(A + (size_t)(bm + lr) * K + k0 + lc);
            float4 a0 = ag[0];
            As[lc + 0][lr] = a0.x; As[lc + 1][lr] = a0.y; As[lc + 2][lr] = a0.z; As[lc + 3][lr] = a0.w;
        }
        {
            int lr = t >> 1, lc = (t & 1) * 8;
            const float4* bg = (const float4*)(Bw + (size_t)(bn + lr) * K + k0 + lc);
            float4 b0 = bg[0], b1 = bg[1];
            Bs[lc + 0][lr] = b0.x; Bs[lc + 1][lr] = b0.y; Bs[lc + 2][lr] = b0.z; Bs[lc + 3][lr] = b0.w;
            Bs[lc + 4][lr] = b1.x; Bs[lc + 5][lr] = b1.y; Bs[lc + 6][lr] = b1.z; Bs[lc + 7][lr] = b1.w;
        }
        __syncthreads();
#pragma unroll
        for (int kk = 0; kk < 16; kk++) {
            float a[MI], b[8];
#pragma unroll
            for (int i = 0; i < MI; i += 4)
                *(float4*)&a[i] = *(const float4*)&As[kk][ty * MI + i];
            *(float4*)&b[0] = *(const float4*)&Bs[kk][tx * 8];
            *(float4*)&b[4] = *(const float4*)&Bs[kk][tx * 8 + 4];
#pragma unroll
            for (int i = 0; i < MI; i++)
#pragma unroll
                for (int j = 0; j < 8; j++) acc[i][j] += a[i] * b[j];
        }
        __syncthreads();
    }

#pragma unroll
    for (int i = 0; i < MI; i++) {
        int row = bm + ty * MI + i;
#pragma unroll
        for (int j = 0; j < 8; j++) {
            int col = bn + tx * 8 + j;
            float v = acc[i][j] + bias1[col];
            if (bias2) v += bias2[col];
            if (RELU) v = fmaxf(v, 0.f);
            C[(size_t)row * N + col] = v;
        }
    }
}

// ======================================================================
// persistent LSTM: 64 CTAs, each owns 4 hidden units (all 4 gates).
// All 256 threads compute gates: K split in two 128-halves, reduced via smem.
// Grid barrier = red-increment + volatile-load poll.
// ======================================================================
#define NBLK 64
#define LSTM_SMEM ((4096 + 8224 + 128 + 1088) * 4)
__device__ __forceinline__ float sigmoidf(float x) { return 1.f / (1.f + expf(-x)); }

__global__ void lstm_kernel(const float* __restrict__ done,
                            const float* __restrict__ h0,
                            const float* __restrict__ c0,
                            const float* __restrict__ whh,
                            float* __restrict__ out) {
    extern __shared__ float sm[];
    float* w_s = sm;             // [k=256][r=16]  (transposed)
    float* h_s = sm + 4096;      // [32][257]
    float* c_s = h_s + 8224;     // [128]  (b*4+jj)
    float* p_s = c_s + 128;      // [2][32][17] partials, padded rows
    int t = threadIdx.x, blk = blockIdx.x;
    int j0 = blk * 4;

    for (int i = t; i < 4096; i += 256) {
        int k = i >> 4, r = i & 15;
        int q = r >> 2, jj = r & 3;
        w_s[i] = whh[(size_t)(q * HID + j0 + jj) * HID + k];
    }
    if (t < 128) {
        int b = t >> 2, jj = t & 3;
        c_s[t] = c0[b * HID + j0 + jj];
    }
    __syncthreads();

    int u = t & 127, half = t >> 7;
    int gb = u & 31, rq = u >> 5;
    unsigned target = 0;

    for (int step = 0; step < TT; step++) {
        // prefetch gx (independent of barrier-protected h)
        float4 acc;
        if (half == 0)
            acc = *(const float4*)&g_gx[(size_t)(step * BB + gb) * 4 * HID + rq * HID + j0];
        else
            acc = make_float4(0.f, 0.f, 0.f, 0.f);

        const float* hsrc = (step == 0) ? h0 : g_h;
        for (int i = t; i < BB * HID; i += 256) {
            int b = i >> 8;
            h_s[b * 257 + (i & 255)] = hsrc[i] * (1.0f - __ldg(&done[step * BB + b]));
        }
        __syncthreads();

        // gates: all 256 threads; thread = (b, gate q, k-half)
        {
            const float* hp = &h_s[gb * 257 + half * 128];
            const float* wp = &w_s[(half * 128) * 16 + rq * 4];
#pragma unroll 8
            for (int k = 0; k < 128; k++) {
                float hv = hp[k];
                float4 wv = *(const float4*)&wp[k * 16];
                acc.x += hv * wv.x;
                acc.y += hv * wv.y;
                acc.z += hv * wv.z;
                acc.w += hv * wv.w;
            }
            float* pp = &p_s[half * 544 + gb * 17 + rq * 4];
            pp[0] = acc.x; pp[1] = acc.y; pp[2] = acc.z; pp[3] = acc.w;
        }
        __syncthreads();

        // update: 128 threads, one (b, jj) each
        if (t < 128) {
            int b = t >> 2, jj = t & 3;
            float m = 1.0f - __ldg(&done[step * BB + b]);
            const float* p0 = &p_s[b * 17];
            const float* p1 = &p_s[544 + b * 17];
            float gi = p0[0 + jj] + p1[0 + jj];
            float gf = p0[4 + jj] + p1[4 + jj];
            float gg = p0[8 + jj] + p1[8 + jj];
            float go = p0[12 + jj] + p1[12 + jj];
            float I = sigmoidf(gi);
            float F = sigmoidf(gf);
            float G = tanhf(gg);
            float O = sigmoidf(go);
            float c_new = F * (m * c_s[t]) + I * G;
            c_s[t] = c_new;
            float h_new = O * tanhf(c_new);
            g_h[b * HID + j0 + jj] = h_new;
            g_hs[(size_t)(step * BB + b) * HID + j0 + jj] = h_new;
            if (step == TT - 1) {
                out[OUT_H + b * HID + j0 + jj] = h_new;
                out[OUT_C + b * HID + j0 + jj] = c_new;
            }
        }
        __threadfence();
        __syncthreads();
        if (t == 0) {
            atomicAdd(&g_bar, 1u);
            target += NBLK;
            while (*(volatile unsigned*)&g_bar < target) { }
        }
        __syncthreads();
    }

    // reset barrier state for next graph replay (last CTA to exit resets)
    if (t == 0) {
        unsigned v = atomicAdd(&g_exit, 1u);
        if (v == NBLK - 1) {
            atomicExch(&g_exit, 0u);
            atomicExch(&g_bar, 0u);
            __threadfence();
        }
    }
}

// ======================================================================
// heads: logits = h@pol_w^T + pol_b ; v = h@val_w^T + val_b
// one warp per row; 8 rows per block
// ======================================================================
__global__ void heads_kernel(const float* __restrict__ pw,
                             const float* __restrict__ pb,
                             const float* __restrict__ vw,
                             const float* __restrict__ vb,
                             float* __restrict__ out) {
    __shared__ float ws[7 * 256];
    int t = threadIdx.x;
    for (int i = t; i < 6 * 256; i += 256) ws[i] = pw[i];
    if (t < 256) ws[1536 + t] = vw[t];
    __syncthreads();

    int warp = t >> 5, lane = t & 31;
    int row = blockIdx.x * 8 + warp;
    const float* hrow = g_hs + (size_t)row * 256;
    float p[7];
#pragma unroll
    for (int a = 0; a < 7; a++) p[a] = 0.f;
    for (int k = lane; k < 256; k += 32) {
        float hv = hrow[k];
#pragma unroll
        for (int a = 0; a < 7; a++) p[a] += hv * ws[a * 256 + k];
    }
#pragma unroll
    for (int a = 0; a < 7; a++)
#pragma unroll
        for (int off = 16; off; off >>= 1)
            p[a] += __shfl_xor_sync(0xffffffffu, p[a], off);
    if (lane == 0) {
#pragma unroll
        for (int a = 0; a < 6; a++) out[(size_t)row * 6 + a] = p[a] + pb[a];
        out[OUT_V + row] = p[6] + vb[0];
    }
}

// ======================================================================
// launch
// ======================================================================
extern "C" void kernel_launch(void* const* d_in, const int* in_sizes, int n_in,
                              void* d_out, int out_size) {
    const float* image = (const float*)d_in[0];
    const float* done  = (const float*)d_in[1];
    const float* h0    = (const float*)d_in[2];
    const float* c0    = (const float*)d_in[3];
    const float* c1w   = (const float*)d_in[4];
    const float* c1b   = (const float*)d_in[5];
    const float* c2w   = (const float*)d_in[6];
    const float* c2b   = (const float*)d_in[7];
    const float* c3w   = (const float*)d_in[8];
    const float* c3b   = (const float*)d_in[9];
    const float* fcw   = (const float*)d_in[10];
    const float* fcb   = (const float*)d_in[11];
    const float* wih   = (const float*)d_in[12];
    const float* whh   = (const float*)d_in[13];
    const float* bih   = (const float*)d_in[14];
    const float* bhh   = (const float*)d_in[15];
    const float* polw  = (const float*)d_in[16];
    const float* polb  = (const float*)d_in[17];
    const float* valw  = (const float*)d_in[18];
    const float* valb  = (const float*)d_in[19];
    float* out = (float*)d_out;

    cudaFuncSetAttribute(conv1_kernel, cudaFuncAttributeMaxDynamicSharedMemorySize, C1_SMEM);
    cudaFuncSetAttribute(conv2_kernel, cudaFuncAttributeMaxDynamicSharedMemorySize, C2_SMEM);
    cudaFuncSetAttribute(conv3_kernel, cudaFuncAttributeMaxDynamicSharedMemorySize, C3_SMEM);
    cudaFuncSetAttribute(lstm_kernel,  cudaFuncAttributeMaxDynamicSharedMemorySize, LSTM_SMEM);

    void *p_c3, *p_feat, *p_gx;
    cudaGetSymbolAddress(&p_c3, g_c3);
    cudaGetSymbolAddress(&p_feat, g_feat);
    cudaGetSymbolAddress(&p_gx, g_gx);

    conv1_kernel<<<NTB, C1_THREADS, C1_SMEM>>>(image, c1w, c1b);
    conv2_kernel<<<NTB, C2_THREADS, C2_SMEM>>>(c2w, c2b);
    conv3_kernel<<<NTB, C3_THREADS, C3_SMEM>>>(c3w, c3b);

    // feats = relu(flat @ fc_w^T + fc_b)   [4096,512]  -- 64x128 tiles -> 256 CTAs
    gemm_kernel<64, true><<<dim3(FEAT / 128, NTB / 64), 256>>>(
        (const float*)p_c3, fcw, fcb, nullptr, (float*)p_feat, NTB, FEAT, FLAT);

    // gates_x = feats @ w_ih^T + b_ih + b_hh   [4096,1024] -- 128x128 tiles -> 256 CTAs
    gemm_kernel<128, false><<<dim3((4 * HID) / 128, NTB / 128), 256>>>(
        (const float*)p_feat, wih, bih, bhh, (float*)p_gx, NTB, 4 * HID, FEAT);

    lstm_kernel<<<NBLK, 256, LSTM_SMEM>>>(done, h0, c0, whh, out);

    heads_kernel<<<NTB / 8, 256>>>(polw, polb, valw, valb, out);
}

// round 3
// speedup vs baseline: 1.3121x; 1.1966x over previous
#include <cuda_runtime.h>
#include <math.h>

// ---------------- problem constants ----------------
#define TT   128
#define BB   32
#define NTB  4096            // T*B
#define HID  256
#define FEAT 512
#define FLAT 3136            // 64*7*7
#define NACT 6

// output layout (flattened tuple): logits[4096*6], v[4096], h[32*256], c[32*256]
#define OUT_V    24576
#define OUT_H    28672
#define OUT_C    36864

// ---------------- scratch (device globals; no allocations allowed) ----------------
__device__ float g_c1[(size_t)NTB*32*20*20];   // 210 MB
__device__ float g_c2[(size_t)NTB*64*9*9];     //  85 MB
__device__ float g_c3[(size_t)NTB*64*7*7];     //  51 MB
__device__ float g_feat[(size_t)NTB*FEAT];     //   8 MB
__device__ float g_gx[(size_t)NTB*4*HID];      //  16 MB
__device__ float g_hs[(size_t)NTB*HID];        //   4 MB
__device__ float g_h[BB*HID];
__device__ unsigned g_bar;
__device__ unsigned g_exit;

// ======================================================================
// conv1: (n,3,84,84)/255 -> (n,32,20,20), k=8 s=4, relu.
// 224 threads; threads 0..199 each compute 2 positions (pos, pos+200)
// -> each weight float4 load feeds 8 FMAs.
// ======================================================================
#define C1_THREADS 224
#define C1_SMEM ((21168 + 6144) * 4)
__global__ void __launch_bounds__(C1_THREADS, 2)
conv1_kernel(const float* __restrict__ img,
             const float* __restrict__ w,
             const float* __restrict__ bias) {
    extern __shared__ float sm[];
    float* im = sm;           // 21168
    float* ws = sm + 21168;   // 6144, layout [c][ky][kx][co]
    int n = blockIdx.x;
    const float* src = img + (size_t)n * 21168;
    for (int i = threadIdx.x; i < 21168; i += C1_THREADS) im[i] = src[i];
    for (int i = threadIdx.x; i < 6144; i += C1_THREADS) {
        int co = i & 31; int rest = i >> 5;
        int kx = rest & 7; rest >>= 3;
        int ky = rest & 7; int c = rest >> 3;
        ws[i] = w[((co * 3 + c) * 8 + ky) * 8 + kx] * (1.0f / 255.0f);
    }
    __syncthreads();

    int t = threadIdx.x;
    if (t < 200) {
        int p1 = t, p2 = t + 200;
        int oy1 = p1 / 20, ox1 = p1 % 20;
        int oy2 = p2 / 20, ox2 = p2 % 20;
        float acc1[32], acc2[32];
#pragma unroll
        for (int i = 0; i < 32; i++) { acc1[i] = 0.f; acc2[i] = 0.f; }
        for (int c = 0; c < 3; c++) {
#pragma unroll
            for (int ky = 0; ky < 8; ky++) {
                const float* ir1 = &im[(c * 84 + oy1 * 4 + ky) * 84 + ox1 * 4];
                const float* ir2 = &im[(c * 84 + oy2 * 4 + ky) * 84 + ox2 * 4];
                float r1[8], r2[8];
#pragma unroll
                for (int kx = 0; kx < 8; kx++) { r1[kx] = ir1[kx]; r2[kx] = ir2[kx]; }
                const float* wrow = &ws[((c * 8 + ky) * 8) * 32];
#pragma unroll
                for (int kx = 0; kx < 8; kx++) {
                    const float4* w4 = (const float4*)(wrow + kx * 32);
                    float a = r1[kx], b = r2[kx];
#pragma unroll
                    for (int q = 0; q < 8; q++) {
                        float4 v = w4[q];
                        acc1[q*4+0] += a * v.x; acc2[q*4+0] += b * v.x;
                        acc1[q*4+1] += a * v.y; acc2[q*4+1] += b * v.y;
                        acc1[q*4+2] += a * v.z; acc2[q*4+2] += b * v.z;
                        acc1[q*4+3] += a * v.w; acc2[q*4+3] += b * v.w;
                    }
                }
            }
        }
        float* d1 = g_c1 + (size_t)n * 12800 + p1;
        float* d2 = g_c1 + (size_t)n * 12800 + p2;
#pragma unroll
        for (int co = 0; co < 32; co++) {
            float bv = bias[co];
            d1[co * 400] = fmaxf(acc1[co] + bv, 0.f);
            d2[co * 400] = fmaxf(acc2[co] + bv, 0.f);
        }
    }
}

// ======================================================================
// conv2: (n,32,20,20) -> (n,64,9,9), k=4 s=2, relu.
// 128 threads; 108 active: thread = (cot of 16co, p<27) computing
// positions p, p+27, p+54  -> 12 FMAs per weight float4 load.
// Weights chunked through smem (8 input channels at a time, 32KB).
// ======================================================================
#define C2_THREADS 128
#define C2_SMEM ((12800 + 8192) * 4)
__global__ void __launch_bounds__(C2_THREADS, 2)
conv2_kernel(const float* __restrict__ w,
             const float* __restrict__ bias) {
    extern __shared__ float sm[];
    float* in = sm;            // 12800
    float* wc = sm + 12800;    // [cc=8][ky][kx][64]
    int n = blockIdx.x;
    const float* src = g_c1 + (size_t)n * 12800;
    for (int i = threadIdx.x; i < 12800; i += C2_THREADS) in[i] = src[i];

    int t = threadIdx.x;
    bool act = t < 108;
    int cot = t / 27, p = t % 27;
    int oy1 = p / 9, ox1 = p % 9;
    int oy2 = (p + 27) / 9, ox2 = (p + 27) % 9;
    int oy3 = (p + 54) / 9, ox3 = (p + 54) % 9;
    float a1[16], a2[16], a3[16];
#pragma unroll
    for (int i = 0; i < 16; i++) { a1[i] = 0.f; a2[i] = 0.f; a3[i] = 0.f; }

    for (int ck = 0; ck < 4; ck++) {
        __syncthreads();
        for (int i = t; i < 8192; i += C2_THREADS) {
            int co = i & 63; int rest = i >> 6;
            int kx = rest & 3; rest >>= 2;
            int ky = rest & 3; int cc = rest >> 2;
            wc[i] = w[((co * 32 + ck * 8 + cc) * 4 + ky) * 4 + kx];
        }
        __syncthreads();
        if (act) {
            for (int cc = 0; cc < 8; cc++) {
                int c = ck * 8 + cc;
#pragma unroll
                for (int ky = 0; ky < 4; ky++) {
                    const float* b1 = &in[(c * 20 + oy1 * 2 + ky) * 20 + ox1 * 2];
                    const float* b2 = &in[(c * 20 + oy2 * 2 + ky) * 20 + ox2 * 2];
                    const float* b3 = &in[(c * 20 + oy3 * 2 + ky) * 20 + ox3 * 2];
                    float r1[4], r2[4], r3[4];
#pragma unroll
                    for (int kx = 0; kx < 4; kx++) { r1[kx]=b1[kx]; r2[kx]=b2[kx]; r3[kx]=b3[kx]; }
#pragma unroll
                    for (int kx = 0; kx < 4; kx++) {
                        const float4* w4 = (const float4*)&wc[((cc * 4 + ky) * 4 + kx) * 64 + cot * 16];
                        float x1 = r1[kx], x2 = r2[kx], x3 = r3[kx];
#pragma unroll
                        for (int q = 0; q < 4; q++) {
                            float4 v = w4[q];
                            a1[q*4+0]+=x1*v.x; a2[q*4+0]+=x2*v.x; a3[q*4+0]+=x3*v.x;
                            a1[q*4+1]+=x1*v.y; a2[q*4+1]+=x2*v.y; a3[q*4+1]+=x3*v.y;
                            a1[q*4+2]+=x1*v.z; a2[q*4+2]+=x2*v.z; a3[q*4+2]+=x3*v.z;
                            a1[q*4+3]+=x1*v.w; a2[q*4+3]+=x2*v.w; a3[q*4+3]+=x3*v.w;
                        }
                    }
                }
            }
        }
    }
    if (act) {
        float* base = g_c2 + (size_t)n * 5184;
#pragma unroll
        for (int i = 0; i < 16; i++) {
            int co = cot * 16 + i;
            float bv = bias[co];
            base[co * 81 + p]      = fmaxf(a1[i] + bv, 0.f);
            base[co * 81 + p + 27] = fmaxf(a2[i] + bv, 0.f);
            base[co * 81 + p + 54] = fmaxf(a3[i] + bv, 0.f);
        }
    }
}

// ======================================================================
// conv3: (n,64,9,9) -> (n,64,7,7), k=3 s=1, relu.
// 224 threads; 200 active: thread = (cot of 8co, p<25) computing
// positions p and p+25 (p=24 single) -> 8 FMAs per weight float4.
// Weights chunked (16 input channels at a time, 37KB).
// ======================================================================
#define C3_THREADS 224
#define C3_SMEM ((5184 + 9216) * 4)
__global__ void __launch_bounds__(C3_THREADS, 2)
conv3_kernel(const float* __restrict__ w,
             const float* __restrict__ bias) {
    extern __shared__ float sm[];
    float* in = sm;            // 5184
    float* wc = sm + 5184;     // [cc=16][ky][kx][64]
    int n = blockIdx.x;
    const float* src = g_c2 + (size_t)n * 5184;
    for (int i = threadIdx.x; i < 5184; i += C3_THREADS) in[i] = src[i];

    int t = threadIdx.x;
    bool act = t < 200;
    int cot = t / 25, p = t % 25;
    bool has2 = p < 24;
    int p2 = has2 ? p + 25 : p;          // dummy alias when absent (computed, not stored)
    int oy1 = p / 7, ox1 = p % 7;
    int oy2 = p2 / 7, ox2 = p2 % 7;
    float a1[8], a2[8];
#pragma unroll
    for (int i = 0; i < 8; i++) { a1[i] = 0.f; a2[i] = 0.f; }

    for (int ck = 0; ck < 4; ck++) {
        __syncthreads();
        for (int i = t; i < 9216; i += C3_THREADS) {
            int co = i & 63; int rest = i >> 6;
            int kx = rest % 3; rest /= 3;
            int ky = rest % 3; int cc = rest / 3;
            wc[i] = w[((co * 64 + ck * 16 + cc) * 3 + ky) * 3 + kx];
        }
        __syncthreads();
        if (act) {
            for (int cc = 0; cc < 16; cc++) {
                int c = ck * 16 + cc;
#pragma unroll
                for (int ky = 0; ky < 3; ky++) {
                    const float* b1 = &in[(c * 9 + oy1 + ky) * 9 + ox1];
                    const float* b2 = &in[(c * 9 + oy2 + ky) * 9 + ox2];
                    float r1[3], r2[3];
#pragma unroll
                    for (int kx = 0; kx < 3; kx++) { r1[kx] = b1[kx]; r2[kx] = b2[kx]; }
#pragma unroll
                    for (int kx = 0; kx < 3; kx++) {
                        const float4* w4 = (const float4*)&wc[((cc * 3 + ky) * 3 + kx) * 64 + cot * 8];
                        float x1 = r1[kx], x2 = r2[kx];
                        float4 v0 = w4[0], v1 = w4[1];
                        a1[0]+=x1*v0.x; a2[0]+=x2*v0.x;
                        a1[1]+=x1*v0.y; a2[1]+=x2*v0.y;
                        a1[2]+=x1*v0.z; a2[2]+=x2*v0.z;
                        a1[3]+=x1*v0.w; a2[3]+=x2*v0.w;
                        a1[4]+=x1*v1.x; a2[4]+=x2*v1.x;
                        a1[5]+=x1*v1.y; a2[5]+=x2*v1.y;
                        a1[6]+=x1*v1.z; a2[6]+=x2*v1.z;
                        a1[7]+=x1*v1.w; a2[7]+=x2*v1.w;
                    }
                }
            }
        }
    }
    if (act) {
        float* base = g_c3 + (size_t)n * 3136;
#pragma unroll
        for (int i = 0; i < 8; i++) {
            int co = cot * 8 + i;
            float bv = bias[co];
            base[co * 49 + p] = fmaxf(a1[i] + bv, 0.f);
            if (has2) base[co * 49 + p + 25] = fmaxf(a2[i] + bv, 0.f);
        }
    }
}

// ======================================================================
// GEMM: C[M,N] = A[M,K] @ Bw[N,K]^T + b1 (+ b2), optional relu
// 128x128 CTA tile, BK=16, 256 threads, double-buffered smem.
// ======================================================================
template <bool RELU>
__global__ void __launch_bounds__(256)
gemm_kernel(const float* __restrict__ A,
            const float* __restrict__ Bw,
            const float* __restrict__ bias1,
            const float* __restrict__ bias2,
            float* __restrict__ C,
            int M, int N, int K) {
    __shared__ float As[2][16][132];
    __shared__ float Bs[2][16][132];
    int bm = blockIdx.y * 128, bn = blockIdx.x * 128;
    int t = threadIdx.x;
    int lr = t >> 1, lc = (t & 1) * 8;
    int tx = t & 15, ty = t >> 4;
    float acc[8][8];
#pragma unroll
    for (int i = 0; i < 8; i++)
#pragma unroll
        for (int j = 0; j < 8; j++) acc[i][j] = 0.f;

    const float* Ap = A + (size_t)(bm + lr) * K + lc;
    const float* Bp = Bw + (size_t)(bn + lr) * K + lc;

    // preload tile 0 into buffer 0
    {
        float4 a0 = *(const float4*)(Ap);
        float4 a1 = *(const float4*)(Ap + 4);
        float4 b0 = *(const float4*)(Bp);
        float4 b1 = *(const float4*)(Bp + 4);
        As[0][lc+0][lr]=a0.x; As[0][lc+1][lr]=a0.y; As[0][lc+2][lr]=a0.z; As[0][lc+3][lr]=a0.w;
        As[0][lc+4][lr]=a1.x; As[0][lc+5][lr]=a1.y; As[0][lc+6][lr]=a1.z; As[0][lc+7][lr]=a1.w;
        Bs[0][lc+0][lr]=b0.x; Bs[0][lc+1][lr]=b0.y; Bs[0][lc+2][lr]=b0.z; Bs[0][lc+3][lr]=b0.w;
        Bs[0][lc+4][lr]=b1.x; Bs[0][lc+5][lr]=b1.y; Bs[0][lc+6][lr]=b1.z; Bs[0][lc+7][lr]=b1.w;
    }
    __syncthreads();

    int cur = 0;
    for (int k0 = 0; k0 < K; k0 += 16) {
        float4 a0, a1, b0, b1;
        bool more = (k0 + 16) < K;
        if (more) {
            a0 = *(const float4*)(Ap + k0 + 16);
            a1 = *(const float4*)(Ap + k0 + 20);
            b0 = *(const float4*)(Bp + k0 + 16);
            b1 = *(const float4*)(Bp + k0 + 20);
        }
#pragma unroll
        for (int kk = 0; kk < 16; kk++) {
            float a[8], b[8];
            *(float4*)&a[0] = *(const float4*)&As[cur][kk][ty * 8];
            *(float4*)&a[4] = *(const float4*)&As[cur][kk][ty * 8 + 4];
            *(float4*)&b[0] = *(const float4*)&Bs[cur][kk][tx * 8];
            *(float4*)&b[4] = *(const float4*)&Bs[cur][kk][tx * 8 + 4];
#pragma unroll
            for (int i = 0; i < 8; i++)
#pragma unroll
                for (int j = 0; j < 8; j++) acc[i][j] += a[i] * b[j];
        }
        if (more) {
            int nxt = cur ^ 1;
            As[nxt][lc+0][lr]=a0.x; As[nxt][lc+1][lr]=a0.y; As[nxt][lc+2][lr]=a0.z; As[nxt][lc+3][lr]=a0.w;
            As[nxt][lc+4][lr]=a1.x; As[nxt][lc+5][lr]=a1.y; As[nxt][lc+6][lr]=a1.z; As[nxt][lc+7][lr]=a1.w;
            Bs[nxt][lc+0][lr]=b0.x; Bs[nxt][lc+1][lr]=b0.y; Bs[nxt][lc+2][lr]=b0.z; Bs[nxt][lc+3][lr]=b0.w;
            Bs[nxt][lc+4][lr]=b1.x; Bs[nxt][lc+5][lr]=b1.y; Bs[nxt][lc+6][lr]=b1.z; Bs[nxt][lc+7][lr]=b1.w;
            __syncthreads();
            cur = nxt;
        }
    }

#pragma unroll
    for (int i = 0; i < 8; i++) {
        int row = bm + ty * 8 + i;
#pragma unroll
        for (int j = 0; j < 8; j++) {
            int col = bn + tx * 8 + j;
            float v = acc[i][j] + bias1[col];
            if (bias2) v += bias2[col];
            if (RELU) v = fmaxf(v, 0.f);
            C[(size_t)row * N + col] = v;
        }
    }
}

// ======================================================================
// persistent LSTM: 128 CTAs, each owns 2 hidden units (all 4 gates).
// 256 threads: gate dot-products K-split in two halves, smem reduce.
// ======================================================================
#define NBLK 128
#define LSTM_SMEM ((2048 + 8224 + 64 + 576) * 4)
__device__ __forceinline__ float sigmoidf(float x) { return 1.f / (1.f + expf(-x)); }

__global__ void __launch_bounds__(256)
lstm_kernel(const float* __restrict__ done,
            const float* __restrict__ h0,
            const float* __restrict__ c0,
            const float* __restrict__ whh,
            float* __restrict__ out) {
    extern __shared__ float sm[];
    float* w_s = sm;             // [k=256][r=8]  (transposed, r = q*2+jj)
    float* h_s = sm + 2048;      // [32][257]
    float* c_s = h_s + 8224;     // [64]  (b*2+jj)
    float* p_s = c_s + 64;       // [2][32][9] partials (8 used + 1 pad)
    int t = threadIdx.x, blk = blockIdx.x;
    int j0 = blk * 2;

    for (int i = t; i < 2048; i += 256) {
        int k = i >> 3, r = i & 7;
        int q = r >> 1, jj = r & 1;
        w_s[i] = whh[(size_t)(q * HID + j0 + jj) * HID + k];
    }
    if (t < 64) {
        int b = t >> 1, jj = t & 1;
        c_s[t] = c0[b * HID + j0 + jj];
    }
    __syncthreads();

    int u = t & 127, half = t >> 7;
    int gb = u & 31, rq = u >> 5;
    unsigned target = 0;

    for (int step = 0; step < TT; step++) {
        float2 acc;
        if (half == 0)
            acc = *(const float2*)&g_gx[(size_t)(step * BB + gb) * 4 * HID + rq * HID + j0];
        else
            acc = make_float2(0.f, 0.f);

        const float* hsrc = (step == 0) ? h0 : g_h;
        for (int i = t; i < BB * HID; i += 256) {
            int b = i >> 8;
            h_s[b * 257 + (i & 255)] = hsrc[i] * (1.0f - __ldg(&done[step * BB + b]));
        }
        __syncthreads();

        {
            const float* hp = &h_s[gb * 257 + half * 128];
            const float* wp = &w_s[(half * 128) * 8 + rq * 2];
#pragma unroll 8
            for (int k = 0; k < 128; k++) {
                float hv = hp[k];
                float2 wv = *(const float2*)&wp[k * 8];
                acc.x += hv * wv.x;
                acc.y += hv * wv.y;
            }
            float* pp = &p_s[half * 288 + gb * 9 + rq * 2];
            pp[0] = acc.x; pp[1] = acc.y;
        }
        __syncthreads();

        if (t < 64) {
            int b = t >> 1, jj = t & 1;
            float m = 1.0f - __ldg(&done[step * BB + b]);
            const float* p0 = &p_s[b * 9];
            const float* p1 = &p_s[288 + b * 9];
            float gi = p0[0 + jj] + p1[0 + jj];
            float gf = p0[2 + jj] + p1[2 + jj];
            float gg = p0[4 + jj] + p1[4 + jj];
            float go = p0[6 + jj] + p1[6 + jj];
            float I = sigmoidf(gi);
            float F = sigmoidf(gf);
            float G = tanhf(gg);
            float O = sigmoidf(go);
            float c_new = F * (m * c_s[t]) + I * G;
            c_s[t] = c_new;
            float h_new = O * tanhf(c_new);
            g_h[b * HID + j0 + jj] = h_new;
            g_hs[(size_t)(step * BB + b) * HID + j0 + jj] = h_new;
            if (step == TT - 1) {
                out[OUT_H + b * HID + j0 + jj] = h_new;
                out[OUT_C + b * HID + j0 + jj] = c_new;
            }
        }
        __threadfence();
        __syncthreads();
        if (t == 0) {
            atomicAdd(&g_bar, 1u);
            target += NBLK;
            while (*(volatile unsigned*)&g_bar < target) { }
        }
        __syncthreads();
    }

    if (t == 0) {
        unsigned v = atomicAdd(&g_exit, 1u);
        if (v == NBLK - 1) {
            atomicExch(&g_exit, 0u);
            atomicExch(&g_bar, 0u);
            __threadfence();
        }
    }
}

// ======================================================================
// heads: logits = h@pol_w^T + pol_b ; v = h@val_w^T + val_b
// ======================================================================
__global__ void heads_kernel(const float* __restrict__ pw,
                             const float* __restrict__ pb,
                             const float* __restrict__ vw,
                             const float* __restrict__ vb,
                             float* __restrict__ out) {
    __shared__ float ws[7 * 256];
    int t = threadIdx.x;
    for (int i = t; i < 6 * 256; i += 256) ws[i] = pw[i];
    if (t < 256) ws[1536 + t] = vw[t];
    __syncthreads();

    int warp = t >> 5, lane = t & 31;
    int row = blockIdx.x * 8 + warp;
    const float* hrow = g_hs + (size_t)row * 256;
    float p[7];
#pragma unroll
    for (int a = 0; a < 7; a++) p[a] = 0.f;
    for (int k = lane; k < 256; k += 32) {
        float hv = hrow[k];
#pragma unroll
        for (int a = 0; a < 7; a++) p[a] += hv * ws[a * 256 + k];
    }
#pragma unroll
    for (int a = 0; a < 7; a++)
#pragma unroll
        for (int off = 16; off; off >>= 1)
            p[a] += __shfl_xor_sync(0xffffffffu, p[a], off);
    if (lane == 0) {
#pragma unroll
        for (int a = 0; a < 6; a++) out[(size_t)row * 6 + a] = p[a] + pb[a];
        out[OUT_V + row] = p[6] + vb[0];
    }
}

// ======================================================================
// launch
// ======================================================================
extern "C" void kernel_launch(void* const* d_in, const int* in_sizes, int n_in,
                              void* d_out, int out_size) {
    const float* image = (const float*)d_in[0];
    const float* done  = (const float*)d_in[1];
    const float* h0    = (const float*)d_in[2];
    const float* c0    = (const float*)d_in[3];
    const float* c1w   = (const float*)d_in[4];
    const float* c1b   = (const float*)d_in[5];
    const float* c2w   = (const float*)d_in[6];
    const float* c2b   = (const float*)d_in[7];
    const float* c3w   = (const float*)d_in[8];
    const float* c3b   = (const float*)d_in[9];
    const float* fcw   = (const float*)d_in[10];
    const float* fcb   = (const float*)d_in[11];
    const float* wih   = (const float*)d_in[12];
    const float* whh   = (const float*)d_in[13];
    const float* bih   = (const float*)d_in[14];
    const float* bhh   = (const float*)d_in[15];
    const float* polw  = (const float*)d_in[16];
    const float* polb  = (const float*)d_in[17];
    const float* valw  = (const float*)d_in[18];
    const float* valb  = (const float*)d_in[19];
    float* out = (float*)d_out;

    cudaFuncSetAttribute(conv1_kernel, cudaFuncAttributeMaxDynamicSharedMemorySize, C1_SMEM);
    cudaFuncSetAttribute(conv2_kernel, cudaFuncAttributeMaxDynamicSharedMemorySize, C2_SMEM);
    cudaFuncSetAttribute(conv3_kernel, cudaFuncAttributeMaxDynamicSharedMemorySize, C3_SMEM);
    cudaFuncSetAttribute(lstm_kernel,  cudaFuncAttributeMaxDynamicSharedMemorySize, LSTM_SMEM);

    void *p_c3, *p_feat, *p_gx;
    cudaGetSymbolAddress(&p_c3, g_c3);
    cudaGetSymbolAddress(&p_feat, g_feat);
    cudaGetSymbolAddress(&p_gx, g_gx);

    conv1_kernel<<<NTB, C1_THREADS, C1_SMEM>>>(image, c1w, c1b);
    conv2_kernel<<<NTB, C2_THREADS, C2_SMEM>>>(c2w, c2b);
    conv3_kernel<<<NTB, C3_THREADS, C3_SMEM>>>(c3w, c3b);

    // feats = relu(flat @ fc_w^T + fc_b)   [4096,512]
    gemm_kernel<true><<<dim3(FEAT / 128, NTB / 128), 256>>>(
        (const float*)p_c3, fcw, fcb, nullptr, (float*)p_feat, NTB, FEAT, FLAT);

    // gates_x = feats @ w_ih^T + b_ih + b_hh   [4096,1024]
    gemm_kernel<false><<<dim3((4 * HID) / 128, NTB / 128), 256>>>(
        (const float*)p_feat, wih, bih, bhh, (float*)p_gx, NTB, 4 * HID, FEAT);

    lstm_kernel<<<NBLK, 256, LSTM_SMEM>>>(done, h0, c0, whh, out);

    heads_kernel<<<NTB / 8, 256>>>(polw, polb, valw, valb, out);
}

// round 4
// speedup vs baseline: 1.4355x; 1.0940x over previous
#include <cuda_runtime.h>
#include <math.h>

// ---------------- problem constants ----------------
#define TT   128
#define BB   32
#define NTB  4096            // T*B
#define HID  256
#define FEAT 512
#define FLAT 3136            // 64*7*7
#define NACT 6

// output layout (flattened tuple): logits[4096*6], v[4096], h[32*256], c[32*256]
#define OUT_V    24576
#define OUT_H    28672
#define OUT_C    36864

// ---------------- packed f32x2 helpers (Blackwell FFMA2 path) ----------------
typedef unsigned long long u64t;
__device__ __forceinline__ u64t pk2(float lo, float hi) {
    u64t r;
    asm("mov.b64 %0, {%1, %2};" : "=l"(r) : "f"(lo), "f"(hi));
    return r;
}
__device__ __forceinline__ void fma2(u64t& d, u64t a, u64t b) {
    asm("fma.rn.f32x2 %0, %1, %2, %0;" : "+l"(d) : "l"(a), "l"(b));
}
__device__ __forceinline__ float2 upk2(u64t v) {
    float2 f;
    asm("mov.b64 {%0, %1}, %2;" : "=f"(f.x), "=f"(f.y) : "l"(v));
    return f;
}

// ---------------- scratch (device globals; no allocations allowed) ----------------
__device__ float g_c1[(size_t)NTB*32*20*20];   // 210 MB
__device__ float g_c2[(size_t)NTB*64*9*9];     //  85 MB
__device__ float g_c3[(size_t)NTB*64*7*7];     //  51 MB
__device__ float g_feat[(size_t)NTB*FEAT];     //   8 MB
__device__ float g_gx[(size_t)NTB*4*HID];      //  16 MB
__device__ float g_hs[(size_t)NTB*HID];        //   4 MB
__device__ float g_h[BB*HID];
__device__ unsigned g_bar;
__device__ unsigned g_exit;

// ======================================================================
// conv1: (n,3,84,84)/255 -> (n,32,20,20), k=8 s=4, relu.
// 224 threads; threads 0..199 compute 2 positions each.
// Inner loop in f32x2: 32 FMA2 per (c,ky,kx) pair-step.
// ======================================================================
#define C1_THREADS 224
#define C1_SMEM ((21168 + 6144) * 4)
__global__ void __launch_bounds__(C1_THREADS, 2)
conv1_kernel(const float* __restrict__ img,
             const float* __restrict__ w,
             const float* __restrict__ bias) {
    extern __shared__ float sm[];
    float* im = sm;           // 21168
    float* ws = sm + 21168;   // 6144, layout [c][ky][kx][co]
    int n = blockIdx.x;
    const float* src = img + (size_t)n * 21168;
    for (int i = threadIdx.x; i < 21168; i += C1_THREADS) im[i] = src[i];
    for (int i = threadIdx.x; i < 6144; i += C1_THREADS) {
        int co = i & 31; int rest = i >> 5;
        int kx = rest & 7; rest >>= 3;
        int ky = rest & 7; int c = rest >> 3;
        ws[i] = w[((co * 3 + c) * 8 + ky) * 8 + kx] * (1.0f / 255.0f);
    }
    __syncthreads();

    int t = threadIdx.x;
    if (t < 200) {
        int p1 = t, p2 = t + 200;
        int oy1 = p1 / 20, ox1 = p1 % 20;
        int oy2 = p2 / 20, ox2 = p2 % 20;
        u64t acc1[16], acc2[16];
        u64t z = pk2(0.f, 0.f);
#pragma unroll
        for (int i = 0; i < 16; i++) { acc1[i] = z; acc2[i] = z; }
        for (int c = 0; c < 3; c++) {
#pragma unroll
            for (int ky = 0; ky < 8; ky++) {
                const float* ir1 = &im[(c * 84 + oy1 * 4 + ky) * 84 + ox1 * 4];
                const float* ir2 = &im[(c * 84 + oy2 * 4 + ky) * 84 + ox2 * 4];
                float r1[8], r2[8];
#pragma unroll
                for (int kx = 0; kx < 8; kx++) { r1[kx] = ir1[kx]; r2[kx] = ir2[kx]; }
                const float* wrow = &ws[((c * 8 + ky) * 8) * 32];
#pragma unroll
                for (int kx = 0; kx < 8; kx++) {
                    const ulonglong2* w2 = (const ulonglong2*)(wrow + kx * 32);
                    u64t xa = pk2(r1[kx], r1[kx]);
                    u64t xb = pk2(r2[kx], r2[kx]);
#pragma unroll
                    for (int q = 0; q < 8; q++) {
                        ulonglong2 v = w2[q];
                        fma2(acc1[q*2+0], xa, v.x); fma2(acc1[q*2+1], xa, v.y);
                        fma2(acc2[q*2+0], xb, v.x); fma2(acc2[q*2+1], xb, v.y);
                    }
                }
            }
        }
        float* d1 = g_c1 + (size_t)n * 12800 + p1;
        float* d2 = g_c1 + (size_t)n * 12800 + p2;
#pragma unroll
        for (int p = 0; p < 16; p++) {
            float2 v1 = upk2(acc1[p]);
            float2 v2 = upk2(acc2[p]);
            int co = p * 2;
            float b0 = bias[co], b1 = bias[co + 1];
            d1[(co+0) * 400] = fmaxf(v1.x + b0, 0.f);
            d1[(co+1) * 400] = fmaxf(v1.y + b1, 0.f);
            d2[(co+0) * 400] = fmaxf(v2.x + b0, 0.f);
            d2[(co+1) * 400] = fmaxf(v2.y + b1, 0.f);
        }
    }
}

// ======================================================================
// conv2: (n,32,20,20) -> (n,64,9,9), k=4 s=2, relu.
// 128 threads; 108 active: (cot of 16co) x (p<27) x 3 positions.
// Weights chunked through smem (8 input channels, 32KB). f32x2 inner.
// ======================================================================
#define C2_THREADS 128
#define C2_SMEM ((12800 + 8192) * 4)
__global__ void __launch_bounds__(C2_THREADS, 2)
conv2_kernel(const float* __restrict__ w,
             const float* __restrict__ bias) {
    extern __shared__ float sm[];
    float* in = sm;            // 12800
    float* wc = sm + 12800;    // [cc=8][ky][kx][64]
    int n = blockIdx.x;
    const float* src = g_c1 + (size_t)n * 12800;
    for (int i = threadIdx.x; i < 12800; i += C2_THREADS) in[i] = src[i];

    int t = threadIdx.x;
    bool act = t < 108;
    int cot = t / 27, p = t % 27;
    int oy1 = p / 9, ox1 = p % 9;
    int oy2 = (p + 27) / 9, ox2 = (p + 27) % 9;
    int oy3 = (p + 54) / 9, ox3 = (p + 54) % 9;
    u64t a1[8], a2[8], a3[8];
    u64t z = pk2(0.f, 0.f);
#pragma unroll
    for (int i = 0; i < 8; i++) { a1[i] = z; a2[i] = z; a3[i] = z; }

    for (int ck = 0; ck < 4; ck++) {
        __syncthreads();
        for (int i = t; i < 8192; i += C2_THREADS) {
            int co = i & 63; int rest = i >> 6;
            int kx = rest & 3; rest >>= 2;
            int ky = rest & 3; int cc = rest >> 2;
            wc[i] = w[((co * 32 + ck * 8 + cc) * 4 + ky) * 4 + kx];
        }
        __syncthreads();
        if (act) {
            for (int cc = 0; cc < 8; cc++) {
                int c = ck * 8 + cc;
#pragma unroll
                for (int ky = 0; ky < 4; ky++) {
                    const float* b1 = &in[(c * 20 + oy1 * 2 + ky) * 20 + ox1 * 2];
                    const float* b2 = &in[(c * 20 + oy2 * 2 + ky) * 20 + ox2 * 2];
                    const float* b3 = &in[(c * 20 + oy3 * 2 + ky) * 20 + ox3 * 2];
                    float r1[4], r2[4], r3[4];
#pragma unroll
                    for (int kx = 0; kx < 4; kx++) { r1[kx]=b1[kx]; r2[kx]=b2[kx]; r3[kx]=b3[kx]; }
#pragma unroll
                    for (int kx = 0; kx < 4; kx++) {
                        const ulonglong2* w2 = (const ulonglong2*)&wc[((cc * 4 + ky) * 4 + kx) * 64 + cot * 16];
                        u64t x1 = pk2(r1[kx], r1[kx]);
                        u64t x2 = pk2(r2[kx], r2[kx]);
                        u64t x3 = pk2(r3[kx], r3[kx]);
                        ulonglong2 v0 = w2[0], v1 = w2[1];
                        fma2(a1[0], x1, v0.x); fma2(a1[1], x1, v0.y);
                        fma2(a1[2], x1, v1.x); fma2(a1[3], x1, v1.y);
                        fma2(a2[0], x2, v0.x); fma2(a2[1], x2, v0.y);
                        fma2(a2[2], x2, v1.x); fma2(a2[3], x2, v1.y);
                        fma2(a3[0], x3, v0.x); fma2(a3[1], x3, v0.y);
                        fma2(a3[2], x3, v1.x); fma2(a3[3], x3, v1.y);
                        const ulonglong2* w2b = w2 + 2;
                        ulonglong2 v2 = w2b[0], v3 = w2b[1];
                        fma2(a1[4], x1, v2.x); fma2(a1[5], x1, v2.y);
                        fma2(a1[6], x1, v3.x); fma2(a1[7], x1, v3.y);
                        fma2(a2[4], x2, v2.x); fma2(a2[5], x2, v2.y);
                        fma2(a2[6], x2, v3.x); fma2(a2[7], x2, v3.y);
                        fma2(a3[4], x3, v2.x); fma2(a3[5], x3, v2.y);
                        fma2(a3[6], x3, v3.x); fma2(a3[7], x3, v3.y);
                    }
                }
            }
        }
    }
    if (act) {
        float* base = g_c2 + (size_t)n * 5184;
#pragma unroll
        for (int i = 0; i < 8; i++) {
            float2 v1 = upk2(a1[i]), v2 = upk2(a2[i]), v3 = upk2(a3[i]);
            int co = cot * 16 + i * 2;
            float b0 = bias[co], b1 = bias[co + 1];
            base[(co+0) * 81 + p]      = fmaxf(v1.x + b0, 0.f);
            base[(co+1) * 81 + p]      = fmaxf(v1.y + b1, 0.f);
            base[(co+0) * 81 + p + 27] = fmaxf(v2.x + b0, 0.f);
            base[(co+1) * 81 + p + 27] = fmaxf(v2.y + b1, 0.f);
            base[(co+0) * 81 + p + 54] = fmaxf(v3.x + b0, 0.f);
            base[(co+1) * 81 + p + 54] = fmaxf(v3.y + b1, 0.f);
        }
    }
}

// ======================================================================
// conv3: (n,64,9,9) -> (n,64,7,7), k=3 s=1, relu.
// 224 threads; 200 active: (cot of 8co) x (p<25) x 2 positions.
// Weights chunked (16 input channels, 37KB). f32x2 inner.
// ======================================================================
#define C3_THREADS 224
#define C3_SMEM ((5184 + 9216) * 4)
__global__ void __launch_bounds__(C3_THREADS, 2)
conv3_kernel(const float* __restrict__ w,
             const float* __restrict__ bias) {
    extern __shared__ float sm[];
    float* in = sm;            // 5184
    float* wc = sm + 5184;     // [cc=16][ky][kx][64]
    int n = blockIdx.x;
    const float* src = g_c2 + (size_t)n * 5184;
    for (int i = threadIdx.x; i < 5184; i += C3_THREADS) in[i] = src[i];

    int t = threadIdx.x;
    bool act = t < 200;
    int cot = t / 25, p = t % 25;
    bool has2 = p < 24;
    int p2 = has2 ? p + 25 : p;
    int oy1 = p / 7, ox1 = p % 7;
    int oy2 = p2 / 7, ox2 = p2 % 7;
    u64t a1[4], a2[4];
    u64t z = pk2(0.f, 0.f);
#pragma unroll
    for (int i = 0; i < 4; i++) { a1[i] = z; a2[i] = z; }

    for (int ck = 0; ck < 4; ck++) {
        __syncthreads();
        for (int i = t; i < 9216; i += C3_THREADS) {
            int co = i & 63; int rest = i >> 6;
            int kx = rest % 3; rest /= 3;
            int ky = rest % 3; int cc = rest / 3;
            wc[i] = w[((co * 64 + ck * 16 + cc) * 3 + ky) * 3 + kx];
        }
        __syncthreads();
        if (act) {
            for (int cc = 0; cc < 16; cc++) {
                int c = ck * 16 + cc;
#pragma unroll
                for (int ky = 0; ky < 3; ky++) {
                    const float* b1 = &in[(c * 9 + oy1 + ky) * 9 + ox1];
                    const float* b2 = &in[(c * 9 + oy2 + ky) * 9 + ox2];
                    float r1[3], r2[3];
#pragma unroll
                    for (int kx = 0; kx < 3; kx++) { r1[kx] = b1[kx]; r2[kx] = b2[kx]; }
#pragma unroll
                    for (int kx = 0; kx < 3; kx++) {
                        const ulonglong2* w2 = (const ulonglong2*)&wc[((cc * 3 + ky) * 3 + kx) * 64 + cot * 8];
                        u64t x1 = pk2(r1[kx], r1[kx]);
                        u64t x2 = pk2(r2[kx], r2[kx]);
                        ulonglong2 v0 = w2[0], v1 = w2[1];
                        fma2(a1[0], x1, v0.x); fma2(a1[1], x1, v0.y);
                        fma2(a1[2], x1, v1.x); fma2(a1[3], x1, v1.y);
                        fma2(a2[0], x2, v0.x); fma2(a2[1], x2, v0.y);
                        fma2(a2[2], x2, v1.x); fma2(a2[3], x2, v1.y);
                    }
                }
            }
        }
    }
    if (act) {
        float* base = g_c3 + (size_t)n * 3136;
#pragma unroll
        for (int i = 0; i < 4; i++) {
            float2 v1 = upk2(a1[i]), v2 = upk2(a2[i]);
            int co = cot * 8 + i * 2;
            float b0 = bias[co], b1 = bias[co + 1];
            base[(co+0) * 49 + p] = fmaxf(v1.x + b0, 0.f);
            base[(co+1) * 49 + p] = fmaxf(v1.y + b1, 0.f);
            if (has2) {
                base[(co+0) * 49 + p + 25] = fmaxf(v2.x + b0, 0.f);
                base[(co+1) * 49 + p + 25] = fmaxf(v2.y + b1, 0.f);
            }
        }
    }
}

// ======================================================================
// GEMM: C[M,N] = A[M,K] @ Bw[N,K]^T + b1 (+ b2), optional relu
// 128x128 CTA tile, BK=16, 256 threads, double-buffered, f32x2 microkernel.
// ======================================================================
template <bool RELU>
__global__ void __launch_bounds__(256)
gemm_kernel(const float* __restrict__ A,
            const float* __restrict__ Bw,
            const float* __restrict__ bias1,
            const float* __restrict__ bias2,
            float* __restrict__ C,
            int M, int N, int K) {
    __shared__ float As[2][16][132];
    __shared__ float Bs[2][16][132];
    int bm = blockIdx.y * 128, bn = blockIdx.x * 128;
    int t = threadIdx.x;
    int lr = t >> 1, lc = (t & 1) * 8;
    int tx = t & 15, ty = t >> 4;
    u64t acc[8][4];
    u64t z = pk2(0.f, 0.f);
#pragma unroll
    for (int i = 0; i < 8; i++)
#pragma unroll
        for (int j = 0; j < 4; j++) acc[i][j] = z;

    const float* Ap = A + (size_t)(bm + lr) * K + lc;
    const float* Bp = Bw + (size_t)(bn + lr) * K + lc;

    {
        float4 a0 = *(const float4*)(Ap);
        float4 a1 = *(const float4*)(Ap + 4);
        float4 b0 = *(const float4*)(Bp);
        float4 b1 = *(const float4*)(Bp + 4);
        As[0][lc+0][lr]=a0.x; As[0][lc+1][lr]=a0.y; As[0][lc+2][lr]=a0.z; As[0][lc+3][lr]=a0.w;
        As[0][lc+4][lr]=a1.x; As[0][lc+5][lr]=a1.y; As[0][lc+6][lr]=a1.z; As[0][lc+7][lr]=a1.w;
        Bs[0][lc+0][lr]=b0.x; Bs[0][lc+1][lr]=b0.y; Bs[0][lc+2][lr]=b0.z; Bs[0][lc+3][lr]=b0.w;
        Bs[0][lc+4][lr]=b1.x; Bs[0][lc+5][lr]=b1.y; Bs[0][lc+6][lr]=b1.z; Bs[0][lc+7][lr]=b1.w;
    }
    __syncthreads();

    int cur = 0;
    for (int k0 = 0; k0 < K; k0 += 16) {
        float4 a0, a1, b0, b1;
        bool more = (k0 + 16) < K;
        if (more) {
            a0 = *(const float4*)(Ap + k0 + 16);
            a1 = *(const float4*)(Ap + k0 + 20);
            b0 = *(const float4*)(Bp + k0 + 16);
            b1 = *(const float4*)(Bp + k0 + 20);
        }
#pragma unroll
        for (int kk = 0; kk < 16; kk++) {
            float a[8];
            *(float4*)&a[0] = *(const float4*)&As[cur][kk][ty * 8];
            *(float4*)&a[4] = *(const float4*)&As[cur][kk][ty * 8 + 4];
            const ulonglong2* bp2 = (const ulonglong2*)&Bs[cur][kk][tx * 8];
            ulonglong2 bb0 = bp2[0], bb1 = bp2[1];
#pragma unroll
            for (int i = 0; i < 8; i++) {
                u64t aa = pk2(a[i], a[i]);
                fma2(acc[i][0], aa, bb0.x);
                fma2(acc[i][1], aa, bb0.y);
                fma2(acc[i][2], aa, bb1.x);
                fma2(acc[i][3], aa, bb1.y);
            }
        }
        if (more) {
            int nxt = cur ^ 1;
            As[nxt][lc+0][lr]=a0.x; As[nxt][lc+1][lr]=a0.y; As[nxt][lc+2][lr]=a0.z; As[nxt][lc+3][lr]=a0.w;
            As[nxt][lc+4][lr]=a1.x; As[nxt][lc+5][lr]=a1.y; As[nxt][lc+6][lr]=a1.z; As[nxt][lc+7][lr]=a1.w;
            Bs[nxt][lc+0][lr]=b0.x; Bs[nxt][lc+1][lr]=b0.y; Bs[nxt][lc+2][lr]=b0.z; Bs[nxt][lc+3][lr]=b0.w;
            Bs[nxt][lc+4][lr]=b1.x; Bs[nxt][lc+5][lr]=b1.y; Bs[nxt][lc+6][lr]=b1.z; Bs[nxt][lc+7][lr]=b1.w;
            __syncthreads();
            cur = nxt;
        }
    }

#pragma unroll
    for (int i = 0; i < 8; i++) {
        int row = bm + ty * 8 + i;
#pragma unroll
        for (int j = 0; j < 4; j++) {
            float2 v = upk2(acc[i][j]);
            int col = bn + tx * 8 + j * 2;
            float r0 = v.x + bias1[col];
            float r1 = v.y + bias1[col + 1];
            if (bias2) { r0 += bias2[col]; r1 += bias2[col + 1]; }
            if (RELU) { r0 = fmaxf(r0, 0.f); r1 = fmaxf(r1, 0.f); }
            C[(size_t)row * N + col]     = r0;
            C[(size_t)row * N + col + 1] = r1;
        }
    }
}

// ======================================================================
// persistent LSTM: 128 CTAs, each owns 2 hidden units (all 4 gates).
// 256 threads: gate dot-products K-split in two halves, smem reduce.
// Recurrent dot in f32x2.
// ======================================================================
#define NBLK 128
#define LSTM_SMEM ((2048 + 8224 + 64 + 576) * 4)
__device__ __forceinline__ float sigmoidf(float x) { return 1.f / (1.f + expf(-x)); }

__global__ void __launch_bounds__(256)
lstm_kernel(const float* __restrict__ done,
            const float* __restrict__ h0,
            const float* __restrict__ c0,
            const float* __restrict__ whh,
            float* __restrict__ out) {
    extern __shared__ float sm[];
    float* w_s = sm;             // [k=256][r=8]  (transposed, r = q*2+jj)
    float* h_s = sm + 2048;      // [32][257]
    float* c_s = h_s + 8224;     // [64]
    float* p_s = c_s + 64;       // [2][32][9] partials
    int t = threadIdx.x, blk = blockIdx.x;
    int j0 = blk * 2;

    for (int i = t; i < 2048; i += 256) {
        int k = i >> 3, r = i & 7;
        int q = r >> 1, jj = r & 1;
        w_s[i] = whh[(size_t)(q * HID + j0 + jj) * HID + k];
    }
    if (t < 64) {
        int b = t >> 1, jj = t & 1;
        c_s[t] = c0[b * HID + j0 + jj];
    }
    __syncthreads();

    int u = t & 127, half = t >> 7;
    int gb = u & 31, rq = u >> 5;
    unsigned target = 0;

    for (int step = 0; step < TT; step++) {
        float2 acc0;
        if (half == 0)
            acc0 = *(const float2*)&g_gx[(size_t)(step * BB + gb) * 4 * HID + rq * HID + j0];
        else
            acc0 = make_float2(0.f, 0.f);
        u64t accp = pk2(acc0.x, acc0.y);

        const float* hsrc = (step == 0) ? h0 : g_h;
        for (int i = t; i < BB * HID; i += 256) {
            int b = i >> 8;
            h_s[b * 257 + (i & 255)] = hsrc[i] * (1.0f - __ldg(&done[step * BB + b]));
        }
        __syncthreads();

        {
            const float* hp = &h_s[gb * 257 + half * 128];
            const float* wp = &w_s[(half * 128) * 8 + rq * 2];
#pragma unroll 8
            for (int k = 0; k < 128; k++) {
                float hv = hp[k];
                u64t hh = pk2(hv, hv);
                u64t wv = *(const u64t*)&wp[k * 8];
                fma2(accp, hh, wv);
            }
            float2 r = upk2(accp);
            float* pp = &p_s[half * 288 + gb * 9 + rq * 2];
            pp[0] = r.x; pp[1] = r.y;
        }
        __syncthreads();

        if (t < 64) {
            int b = t >> 1, jj = t & 1;
            float m = 1.0f - __ldg(&done[step * BB + b]);
            const float* p0 = &p_s[b * 9];
            const float* p1 = &p_s[288 + b * 9];
            float gi = p0[0 + jj] + p1[0 + jj];
            float gf = p0[2 + jj] + p1[2 + jj];
            float gg = p0[4 + jj] + p1[4 + jj];
            float go = p0[6 + jj] + p1[6 + jj];
            float I = sigmoidf(gi);
            float F = sigmoidf(gf);
            float G = tanhf(gg);
            float O = sigmoidf(go);
            float c_new = F * (m * c_s[t]) + I * G;
            c_s[t] = c_new;
            float h_new = O * tanhf(c_new);
            g_h[b * HID + j0 + jj] = h_new;
            g_hs[(size_t)(step * BB + b) * HID + j0 + jj] = h_new;
            if (step == TT - 1) {
                out[OUT_H + b * HID + j0 + jj] = h_new;
                out[OUT_C + b * HID + j0 + jj] = c_new;
            }
        }
        __threadfence();
        __syncthreads();
        if (t == 0) {
            atomicAdd(&g_bar, 1u);
            target += NBLK;
            while (*(volatile unsigned*)&g_bar < target) { }
        }
        __syncthreads();
    }

    if (t == 0) {
        unsigned v = atomicAdd(&g_exit, 1u);
        if (v == NBLK - 1) {
            atomicExch(&g_exit, 0u);
            atomicExch(&g_bar, 0u);
            __threadfence();
        }
    }
}

// ======================================================================
// heads: logits = h@pol_w^T + pol_b ; v = h@val_w^T + val_b
// ======================================================================
__global__ void heads_kernel(const float* __restrict__ pw,
                             const float* __restrict__ pb,
                             const float* __restrict__ vw,
                             const float* __restrict__ vb,
                             float* __restrict__ out) {
    __shared__ float ws[7 * 256];
    int t = threadIdx.x;
    for (int i = t; i < 6 * 256; i += 256) ws[i] = pw[i];
    if (t < 256) ws[1536 + t] = vw[t];
    __syncthreads();

    int warp = t >> 5, lane = t & 31;
    int row = blockIdx.x * 8 + warp;
    const float* hrow = g_hs + (size_t)row * 256;
    float p[7];
#pragma unroll
    for (int a = 0; a < 7; a++) p[a] = 0.f;
    for (int k = lane; k < 256; k += 32) {
        float hv = hrow[k];
#pragma unroll
        for (int a = 0; a < 7; a++) p[a] += hv * ws[a * 256 + k];
    }
#pragma unroll
    for (int a = 0; a < 7; a++)
#pragma unroll
        for (int off = 16; off; off >>= 1)
            p[a] += __shfl_xor_sync(0xffffffffu, p[a], off);
    if (lane == 0) {
#pragma unroll
        for (int a = 0; a < 6; a++) out[(size_t)row * 6 + a] = p[a] + pb[a];
        out[OUT_V + row] = p[6] + vb[0];
    }
}

// ======================================================================
// launch
// ======================================================================
extern "C" void kernel_launch(void* const* d_in, const int* in_sizes, int n_in,
                              void* d_out, int out_size) {
    const float* image = (const float*)d_in[0];
    const float* done  = (const float*)d_in[1];
    const float* h0    = (const float*)d_in[2];
    const float* c0    = (const float*)d_in[3];
    const float* c1w   = (const float*)d_in[4];
    const float* c1b   = (const float*)d_in[5];
    const float* c2w   = (const float*)d_in[6];
    const float* c2b   = (const float*)d_in[7];
    const float* c3w   = (const float*)d_in[8];
    const float* c3b   = (const float*)d_in[9];
    const float* fcw   = (const float*)d_in[10];
    const float* fcb   = (const float*)d_in[11];
    const float* wih   = (const float*)d_in[12];
    const float* whh   = (const float*)d_in[13];
    const float* bih   = (const float*)d_in[14];
    const float* bhh   = (const float*)d_in[15];
    const float* polw  = (const float*)d_in[16];
    const float* polb  = (const float*)d_in[17];
    const float* valw  = (const float*)d_in[18];
    const float* valb  = (const float*)d_in[19];
    float* out = (float*)d_out;

    cudaFuncSetAttribute(conv1_kernel, cudaFuncAttributeMaxDynamicSharedMemorySize, C1_SMEM);
    cudaFuncSetAttribute(conv2_kernel, cudaFuncAttributeMaxDynamicSharedMemorySize, C2_SMEM);
    cudaFuncSetAttribute(conv3_kernel, cudaFuncAttributeMaxDynamicSharedMemorySize, C3_SMEM);
    cudaFuncSetAttribute(lstm_kernel,  cudaFuncAttributeMaxDynamicSharedMemorySize, LSTM_SMEM);

    void *p_c3, *p_feat, *p_gx;
    cudaGetSymbolAddress(&p_c3, g_c3);
    cudaGetSymbolAddress(&p_feat, g_feat);
    cudaGetSymbolAddress(&p_gx, g_gx);

    conv1_kernel<<<NTB, C1_THREADS, C1_SMEM>>>(image, c1w, c1b);
    conv2_kernel<<<NTB, C2_THREADS, C2_SMEM>>>(c2w, c2b);
    conv3_kernel<<<NTB, C3_THREADS, C3_SMEM>>>(c3w, c3b);

    // feats = relu(flat @ fc_w^T + fc_b)   [4096,512]
    gemm_kernel<true><<<dim3(FEAT / 128, NTB / 128), 256>>>(
        (const float*)p_c3, fcw, fcb, nullptr, (float*)p_feat, NTB, FEAT, FLAT);

    // gates_x = feats @ w_ih^T + b_ih + b_hh   [4096,1024]
    gemm_kernel<false><<<dim3((4 * HID) / 128, NTB / 128), 256>>>(
        (const float*)p_feat, wih, bih, bhh, (float*)p_gx, NTB, 4 * HID, FEAT);

    lstm_kernel<<<NBLK, 256, LSTM_SMEM>>>(done, h0, c0, whh, out);

    heads_kernel<<<NTB / 8, 256>>>(polw, polb, valw, valb, out);
}